// round 1
// baseline (speedup 1.0000x reference)
#include <cuda_runtime.h>
#include <math.h>

// Problem constants (fixed by the reference)
constexpr int BATCH = 8;
constexpr int HEADS = 16;
constexpr int SEQ   = 1024;
constexpr int HDIM  = 64;
constexpr int BS    = 32;            // block size (both dims)
constexpr int NB    = SEQ / BS;      // 32 blocks per side

// Block bitmask: for (h, qi) bit j set => block (qi, j) active (incl. forced diagonal).
__device__ unsigned g_bm[HEADS * NB];

// ---------------------------------------------------------------------------
// Kernel 1: pool the [H, S, S] float mask into per-(h, q-block) bitmasks.
// Grid: (HEADS, NB), 256 threads. Each thread scans a 32-row x 4-col strip.
// ---------------------------------------------------------------------------
__global__ void block_mask_kernel(const float* __restrict__ mask) {
    const int h  = blockIdx.x;
    const int bi = blockIdx.y;
    const int t  = threadIdx.x;          // 0..255
    __shared__ unsigned sbits;
    if (t == 0) sbits = 0u;
    __syncthreads();

    const int col = t * 4;               // 256 threads * 4 cols = 1024 cols
    const float* base = mask + ((size_t)h * SEQ + (size_t)bi * BS) * SEQ;

    bool any = false;
    #pragma unroll 4
    for (int r = 0; r < BS; ++r) {
        float4 vv = *reinterpret_cast<const float4*>(base + (size_t)r * SEQ + col);
        any |= (vv.x != 0.f) | (vv.y != 0.f) | (vv.z != 0.f) | (vv.w != 0.f);
    }
    if (any) atomicOr(&sbits, 1u << (col >> 5));
    __syncthreads();

    if (t == 0) g_bm[h * NB + bi] = sbits | (1u << bi);   // diagonal always on
}

// ---------------------------------------------------------------------------
// Kernel 2: block-sparse causal flash attention, fp32 SIMT.
// Grid: (NB, BATCH*HEADS); 256 threads per CTA.
// Thread (r = t>>3, c = t&7): q-row r of the tile, score cols {c, c+8, c+16, c+24},
// output dims [c*8, c*8+8).
// ---------------------------------------------------------------------------
__global__ __launch_bounds__(256, 2)
void attn_kernel(const float* __restrict__ q,
                 const float* __restrict__ k,
                 const float* __restrict__ v,
                 float* __restrict__ out) {
    const int qi = blockIdx.x;              // q block index 0..31
    const int bh = blockIdx.y;              // 0..127
    const int h  = bh & (HEADS - 1);
    const int t  = threadIdx.x;
    const int r  = t >> 3;                  // 0..31 : q row within tile
    const int c  = t & 7;                   // 0..7

    __shared__ float sK[BS][HDIM];          // 8 KB
    __shared__ float sV[BS][HDIM];          // 8 KB
    __shared__ float sP[BS][BS + 1];        // padded to kill write conflicts

    const size_t head_off = (size_t)bh * SEQ * HDIM;

    // Cache this thread's Q row (64 floats) in registers.
    float4 qreg[16];
    {
        const float* qrow = q + head_off + (size_t)(qi * BS + r) * HDIM;
        #pragma unroll
        for (int i = 0; i < 16; ++i)
            qreg[i] = *reinterpret_cast<const float4*>(qrow + i * 4);
    }

    float m = -INFINITY;
    float l = 0.f;
    float acc[8];
    #pragma unroll
    for (int i = 0; i < 8; ++i) acc[i] = 0.f;

    const unsigned bits = g_bm[h * NB + qi];

    for (int j = 0; j <= qi; ++j) {
        if (!((bits >> j) & 1u)) continue;

        // --- stage K and V tiles (32x64 f32 each, fully coalesced float4) ---
        {
            const float4* kg = reinterpret_cast<const float4*>(k + head_off + (size_t)j * BS * HDIM);
            const float4* vg = reinterpret_cast<const float4*>(v + head_off + (size_t)j * BS * HDIM);
            float4* ks = reinterpret_cast<float4*>(&sK[0][0]);
            float4* vs = reinterpret_cast<float4*>(&sV[0][0]);
            ks[t]       = kg[t];
            ks[t + 256] = kg[t + 256];
            vs[t]       = vg[t];
            vs[t + 256] = vg[t + 256];
        }
        __syncthreads();

        // --- scores for 4 columns: dot(q_row, k_col) ---
        float s0 = 0.f, s1 = 0.f, s2 = 0.f, s3 = 0.f;
        #pragma unroll
        for (int i = 0; i < 16; ++i) {
            const float4 a  = qreg[i];
            const float4 k0 = *reinterpret_cast<const float4*>(&sK[c     ][i * 4]);
            const float4 k1 = *reinterpret_cast<const float4*>(&sK[c +  8][i * 4]);
            const float4 k2 = *reinterpret_cast<const float4*>(&sK[c + 16][i * 4]);
            const float4 k3 = *reinterpret_cast<const float4*>(&sK[c + 24][i * 4]);
            s0 += a.x * k0.x + a.y * k0.y + a.z * k0.z + a.w * k0.w;
            s1 += a.x * k1.x + a.y * k1.y + a.z * k1.z + a.w * k1.w;
            s2 += a.x * k2.x + a.y * k2.y + a.z * k2.z + a.w * k2.w;
            s3 += a.x * k3.x + a.y * k3.y + a.z * k3.z + a.w * k3.w;
        }

        // Element-wise causal mask only on the diagonal block.
        if (j == qi) {
            if (c      > r) s0 = -INFINITY;
            if (c +  8 > r) s1 = -INFINITY;
            if (c + 16 > r) s2 = -INFINITY;
            if (c + 24 > r) s3 = -INFINITY;
        }

        // --- online softmax: reduce over the 8 threads of this row ---
        float ms = fmaxf(fmaxf(s0, s1), fmaxf(s2, s3));
        #pragma unroll
        for (int off = 4; off; off >>= 1)
            ms = fmaxf(ms, __shfl_xor_sync(0xffffffffu, ms, off, 8));

        const float mn    = fmaxf(m, ms);
        const float scale = __expf(m - mn);       // m=-inf first time -> 0
        const float p0 = __expf(s0 - mn);
        const float p1 = __expf(s1 - mn);
        const float p2 = __expf(s2 - mn);
        const float p3 = __expf(s3 - mn);

        float lb = p0 + p1 + p2 + p3;
        #pragma unroll
        for (int off = 4; off; off >>= 1)
            lb += __shfl_xor_sync(0xffffffffu, lb, off, 8);

        l = l * scale + lb;
        m = mn;
        #pragma unroll
        for (int i = 0; i < 8; ++i) acc[i] *= scale;

        sP[r][c     ] = p0;
        sP[r][c +  8] = p1;
        sP[r][c + 16] = p2;
        sP[r][c + 24] = p3;
        __syncthreads();

        // --- PV accumulate: 8 output dims per thread over 32 k-rows ---
        #pragma unroll
        for (int col = 0; col < BS; ++col) {
            const float  p  = sP[r][col];
            const float4 v0 = *reinterpret_cast<const float4*>(&sV[col][c * 8]);
            const float4 v1 = *reinterpret_cast<const float4*>(&sV[col][c * 8 + 4]);
            acc[0] += p * v0.x;  acc[1] += p * v0.y;
            acc[2] += p * v0.z;  acc[3] += p * v0.w;
            acc[4] += p * v1.x;  acc[5] += p * v1.y;
            acc[6] += p * v1.z;  acc[7] += p * v1.w;
        }
        __syncthreads();   // protect sK/sV/sP before next iteration's writes
    }

    // --- finalize and store (diagonal block guarantees l > 0) ---
    const float invl = 1.f / l;
    float* orow = out + head_off + (size_t)(qi * BS + r) * HDIM + c * 8;
    float4 o0, o1;
    o0.x = acc[0] * invl; o0.y = acc[1] * invl;
    o0.z = acc[2] * invl; o0.w = acc[3] * invl;
    o1.x = acc[4] * invl; o1.y = acc[5] * invl;
    o1.z = acc[6] * invl; o1.w = acc[7] * invl;
    *reinterpret_cast<float4*>(orow)     = o0;
    *reinterpret_cast<float4*>(orow + 4) = o1;
}

// ---------------------------------------------------------------------------
extern "C" void kernel_launch(void* const* d_in, const int* in_sizes, int n_in,
                              void* d_out, int out_size) {
    (void)in_sizes; (void)n_in; (void)out_size;
    const float* q    = (const float*)d_in[0];
    const float* k    = (const float*)d_in[1];
    const float* v    = (const float*)d_in[2];
    const float* mask = (const float*)d_in[3];
    float* out        = (float*)d_out;

    block_mask_kernel<<<dim3(HEADS, NB), 256>>>(mask);
    attn_kernel<<<dim3(NB, BATCH * HEADS), 256>>>(q, k, v, out);
}

// round 2
// speedup vs baseline: 4.1647x; 4.1647x over previous
#include <cuda_runtime.h>
#include <math.h>

// Problem constants (fixed by the reference)
constexpr int BATCH = 8;
constexpr int HEADS = 16;
constexpr int SEQ   = 1024;
constexpr int HDIM  = 64;
constexpr int BS    = 32;            // block size (both dims)
constexpr int NB    = SEQ / BS;      // 32 blocks per side

constexpr int KPAD  = HDIM + 4;      // 68 floats: padded row stride (bank-conflict free)
constexpr int PPAD  = BS + 4;        // 36 floats: padded probs row (float4-aligned)

// Block bitmask: for (h, qi) bit j set => block (qi, j) active (incl. forced diagonal).
__device__ unsigned g_bm[HEADS * NB];

// ---------------------------------------------------------------------------
// Kernel 1: pool the [H, S, S] float mask into per-(h, q-block) bitmasks.
// ---------------------------------------------------------------------------
__global__ void block_mask_kernel(const float* __restrict__ mask) {
    const int h  = blockIdx.x;
    const int bi = blockIdx.y;
    const int t  = threadIdx.x;          // 0..255
    __shared__ unsigned sbits;
    if (t == 0) sbits = 0u;
    __syncthreads();

    const int col = t * 4;               // 256 threads * 4 cols = 1024 cols
    const float* base = mask + ((size_t)h * SEQ + (size_t)bi * BS) * SEQ;

    bool any = false;
    #pragma unroll 4
    for (int r = 0; r < BS; ++r) {
        float4 vv = *reinterpret_cast<const float4*>(base + (size_t)r * SEQ + col);
        any |= (vv.x != 0.f) | (vv.y != 0.f) | (vv.z != 0.f) | (vv.w != 0.f);
    }
    if (any) atomicOr(&sbits, 1u << (col >> 5));
    __syncthreads();

    if (t == 0) g_bm[h * NB + bi] = sbits | (1u << bi);   // diagonal always on
}

// ---------------------------------------------------------------------------
// Kernel 2: block-sparse causal flash attention, fp32 SIMT, conflict-free smem.
// Grid: (NB, BATCH*HEADS); 256 threads per CTA.
// Thread (r = t>>3, c = t&7): q-row r, score cols {c, c+8, c+16, c+24},
// output dims {4c..4c+3} and {32+4c..32+4c+3}.
// ---------------------------------------------------------------------------
__global__ __launch_bounds__(256, 2)
void attn_kernel(const float* __restrict__ q,
                 const float* __restrict__ k,
                 const float* __restrict__ v,
                 float* __restrict__ out) {
    const int qi = blockIdx.x;              // q block index 0..31
    const int bh = blockIdx.y;              // 0..127
    const int h  = bh & (HEADS - 1);
    const int t  = threadIdx.x;
    const int r  = t >> 3;                  // 0..31 : q row within tile
    const int c  = t & 7;                   // 0..7

    __shared__ float sK[BS * KPAD];         // 8.5 KB, padded rows
    __shared__ float sV[BS * KPAD];         // 8.5 KB, padded rows
    __shared__ float sP[BS * PPAD];         // padded probs

    const size_t head_off = (size_t)bh * SEQ * HDIM;

    // Cache this thread's Q row (64 floats) in registers.
    float4 qreg[16];
    {
        const float* qrow = q + head_off + (size_t)(qi * BS + r) * HDIM;
        #pragma unroll
        for (int i = 0; i < 16; ++i)
            qreg[i] = *reinterpret_cast<const float4*>(qrow + i * 4);
    }

    float m = -INFINITY;
    float l = 0.f;
    float accL[4], accH[4];
    #pragma unroll
    for (int i = 0; i < 4; ++i) { accL[i] = 0.f; accH[i] = 0.f; }

    const unsigned bits = g_bm[h * NB + qi];

    const float4* sK4 = reinterpret_cast<const float4*>(sK);   // stride 17 per row
    const float4* sV4 = reinterpret_cast<const float4*>(sV);
    const float4* sP4row = reinterpret_cast<const float4*>(sP + r * PPAD);

    for (int j = 0; j <= qi; ++j) {
        if (!((bits >> j) & 1u)) continue;

        // --- stage K and V tiles into padded smem (coalesced float4) ---
        {
            const float4* kg = reinterpret_cast<const float4*>(k + head_off + (size_t)j * BS * HDIM);
            const float4* vg = reinterpret_cast<const float4*>(v + head_off + (size_t)j * BS * HDIM);
            float4* ks = reinterpret_cast<float4*>(sK);
            float4* vs = reinterpret_cast<float4*>(sV);
            // idx -> row = idx>>4, col4 = idx&15; padded float4 index = row*17 + col4
            int i0 = t,      p0 = (i0 >> 4) * 17 + (i0 & 15);
            int i1 = t + 256, p1 = (i1 >> 4) * 17 + (i1 & 15);
            ks[p0] = kg[i0];  ks[p1] = kg[i1];
            vs[p0] = vg[i0];  vs[p1] = vg[i1];
        }
        __syncthreads();

        // --- scores for 4 columns: dot(q_row, k_col); conflict-free K reads ---
        float s0 = 0.f, s1 = 0.f, s2 = 0.f, s3 = 0.f;
        #pragma unroll
        for (int i = 0; i < 16; ++i) {
            const float4 a  = qreg[i];
            const float4 k0 = sK4[(c     ) * 17 + i];
            const float4 k1 = sK4[(c +  8) * 17 + i];
            const float4 k2 = sK4[(c + 16) * 17 + i];
            const float4 k3 = sK4[(c + 24) * 17 + i];
            s0 += a.x * k0.x + a.y * k0.y + a.z * k0.z + a.w * k0.w;
            s1 += a.x * k1.x + a.y * k1.y + a.z * k1.z + a.w * k1.w;
            s2 += a.x * k2.x + a.y * k2.y + a.z * k2.z + a.w * k2.w;
            s3 += a.x * k3.x + a.y * k3.y + a.z * k3.z + a.w * k3.w;
        }

        // Element-wise causal mask only on the diagonal block.
        if (j == qi) {
            if (c      > r) s0 = -INFINITY;
            if (c +  8 > r) s1 = -INFINITY;
            if (c + 16 > r) s2 = -INFINITY;
            if (c + 24 > r) s3 = -INFINITY;
        }

        // --- online softmax: reduce over the 8 threads of this row ---
        float ms = fmaxf(fmaxf(s0, s1), fmaxf(s2, s3));
        #pragma unroll
        for (int off = 4; off; off >>= 1)
            ms = fmaxf(ms, __shfl_xor_sync(0xffffffffu, ms, off, 8));

        const float mn    = fmaxf(m, ms);
        const float scale = __expf(m - mn);       // m=-inf first time -> 0
        const float p0 = __expf(s0 - mn);
        const float p1 = __expf(s1 - mn);
        const float p2 = __expf(s2 - mn);
        const float p3 = __expf(s3 - mn);

        float lb = p0 + p1 + p2 + p3;
        #pragma unroll
        for (int off = 4; off; off >>= 1)
            lb += __shfl_xor_sync(0xffffffffu, lb, off, 8);

        l = l * scale + lb;
        m = mn;
        #pragma unroll
        for (int i = 0; i < 4; ++i) { accL[i] *= scale; accH[i] *= scale; }

        sP[r * PPAD + c     ] = p0;
        sP[r * PPAD + c +  8] = p1;
        sP[r * PPAD + c + 16] = p2;
        sP[r * PPAD + c + 24] = p3;
        __syncthreads();

        // --- PV accumulate: dims {4c..4c+3} and {32+4c..32+4c+3} per thread ---
        #pragma unroll
        for (int kk = 0; kk < 8; ++kk) {
            const float4 p4 = sP4row[kk];          // probs for cols 4kk..4kk+3
            const int col0 = 4 * kk;
            #pragma unroll
            for (int u = 0; u < 4; ++u) {
                const float p = (u == 0) ? p4.x : (u == 1) ? p4.y : (u == 2) ? p4.z : p4.w;
                const int base = (col0 + u) * 17;
                const float4 vlo = sV4[base + c];       // dims 4c..4c+3
                const float4 vhi = sV4[base + 8 + c];   // dims 32+4c..32+4c+3
                accL[0] += p * vlo.x;  accL[1] += p * vlo.y;
                accL[2] += p * vlo.z;  accL[3] += p * vlo.w;
                accH[0] += p * vhi.x;  accH[1] += p * vhi.y;
                accH[2] += p * vhi.z;  accH[3] += p * vhi.w;
            }
        }
        __syncthreads();   // protect sK/sV/sP before next iteration's writes
    }

    // --- finalize and store (diagonal block guarantees l > 0) ---
    const float invl = 1.f / l;
    float* orow = out + head_off + (size_t)(qi * BS + r) * HDIM;
    float4 o0, o1;
    o0.x = accL[0] * invl; o0.y = accL[1] * invl;
    o0.z = accL[2] * invl; o0.w = accL[3] * invl;
    o1.x = accH[0] * invl; o1.y = accH[1] * invl;
    o1.z = accH[2] * invl; o1.w = accH[3] * invl;
    *reinterpret_cast<float4*>(orow + 4 * c)      = o0;
    *reinterpret_cast<float4*>(orow + 32 + 4 * c) = o1;
}

// ---------------------------------------------------------------------------
extern "C" void kernel_launch(void* const* d_in, const int* in_sizes, int n_in,
                              void* d_out, int out_size) {
    (void)in_sizes; (void)n_in; (void)out_size;
    const float* q    = (const float*)d_in[0];
    const float* k    = (const float*)d_in[1];
    const float* v    = (const float*)d_in[2];
    const float* mask = (const float*)d_in[3];
    float* out        = (float*)d_out;

    block_mask_kernel<<<dim3(HEADS, NB), 256>>>(mask);
    attn_kernel<<<dim3(NB, BATCH * HEADS), 256>>>(q, k, v, out);
}

// round 3
// speedup vs baseline: 7.1567x; 1.7184x over previous
#include <cuda_runtime.h>
#include <math.h>
#include <stdint.h>

constexpr int BATCH = 8;
constexpr int HEADS = 16;
constexpr int SEQ   = 1024;
constexpr int HDIM  = 64;
constexpr int BS    = 32;
constexpr int NB    = SEQ / BS;

constexpr int KP = 68;   // sK row stride (floats): score B-frag loads conflict-free
constexpr int VP = 72;   // sV row stride: PV B-frag loads conflict-free
constexpr int SP = 40;   // sS row stride: softmax scalar reads conflict-free
constexpr int PP = 36;   // sPhi/sPlo row stride: PV A-frag loads conflict-free

__device__ unsigned g_bm[HEADS * NB];

// ---------------------------------------------------------------------------
__global__ void block_mask_kernel(const float* __restrict__ mask) {
    const int h  = blockIdx.x;
    const int bi = blockIdx.y;
    const int t  = threadIdx.x;
    __shared__ unsigned sbits;
    if (t == 0) sbits = 0u;
    __syncthreads();

    const int col = t * 4;
    const float* base = mask + ((size_t)h * SEQ + (size_t)bi * BS) * SEQ;
    bool any = false;
    #pragma unroll 4
    for (int r = 0; r < BS; ++r) {
        float4 vv = *reinterpret_cast<const float4*>(base + (size_t)r * SEQ + col);
        any |= (vv.x != 0.f) | (vv.y != 0.f) | (vv.z != 0.f) | (vv.w != 0.f);
    }
    if (any) atomicOr(&sbits, 1u << (col >> 5));
    __syncthreads();
    if (t == 0) g_bm[h * NB + bi] = sbits | (1u << bi);
}

// ---------------------------------------------------------------------------
__device__ __forceinline__ unsigned f2tf32(float x) {
    unsigned r;
    asm("cvt.rna.tf32.f32 %0, %1;" : "=r"(r) : "f"(x));
    return r;
}
__device__ __forceinline__ void split_tf32(float x, unsigned& hi, unsigned& lo) {
    hi = f2tf32(x);
    lo = f2tf32(x - __uint_as_float(hi));
}
__device__ __forceinline__ void mma_tf32(float* d, const unsigned* a, unsigned b0, unsigned b1) {
    asm volatile(
        "mma.sync.aligned.m16n8k8.row.col.f32.tf32.tf32.f32 "
        "{%0,%1,%2,%3},{%4,%5,%6,%7},{%8,%9},{%0,%1,%2,%3};"
        : "+f"(d[0]), "+f"(d[1]), "+f"(d[2]), "+f"(d[3])
        : "r"(a[0]), "r"(a[1]), "r"(a[2]), "r"(a[3]), "r"(b0), "r"(b1));
}

// ---------------------------------------------------------------------------
// Block-sparse causal flash attention via mma.sync tf32 (3-pass = fp32 accuracy).
// Grid (NB, BATCH*HEADS), 256 threads = 8 warps.
// Score tile per warp: rows 16*wr.., cols 8*wc..  (wr = w>>2, wc = w&3)
// PV tile per warp:    rows 16*wr.., dims 16*wc + {0,8}
// Softmax: thread (r = t>>3, c = t&7) owns score row r, cols {c,c+8,c+16,c+24}.
// ---------------------------------------------------------------------------
__global__ __launch_bounds__(256, 2)
void attn_kernel(const float* __restrict__ q,
                 const float* __restrict__ k,
                 const float* __restrict__ v,
                 float* __restrict__ out) {
    const int qi = blockIdx.x;
    const int bh = blockIdx.y;
    const int h  = bh & (HEADS - 1);
    const int t  = threadIdx.x;
    const int w    = t >> 5;
    const int lane = t & 31;
    const int g  = lane >> 2;      // 0..7
    const int tg = lane & 3;       // 0..3
    const int wr = w >> 2;         // 0..1
    const int wc = w & 3;          // 0..3
    const int r  = t >> 3;         // 0..31 (softmax row)
    const int c  = t & 7;          // 0..7

    __shared__ float sK[BS * KP];
    __shared__ float sV[BS * VP];
    __shared__ float sS[BS * SP];
    __shared__ float sPhi[BS * PP];
    __shared__ float sPlo[BS * PP];
    __shared__ float sRow[BS];     // per-row scale factor / inv-l

    const size_t head_off = (size_t)bh * SEQ * HDIM;

    // --- Q fragments (hi/lo tf32), loaded once ---
    // a0=(g,tg) a1=(g+8,tg) a2=(g,tg+4) a3=(g+8,tg+4), per 8-dim chunk kc.
    unsigned qhi[8][4], qlo[8][4];
    {
        const int row0 = qi * BS + 16 * wr + g;
        const float* q0 = q + head_off + (size_t)row0 * HDIM;
        const float* q1 = q0 + 8 * HDIM;
        #pragma unroll
        for (int kc = 0; kc < 8; ++kc) {
            const int c0 = 8 * kc + tg;
            split_tf32(q0[c0],     qhi[kc][0], qlo[kc][0]);
            split_tf32(q1[c0],     qhi[kc][1], qlo[kc][1]);
            split_tf32(q0[c0 + 4], qhi[kc][2], qlo[kc][2]);
            split_tf32(q1[c0 + 4], qhi[kc][3], qlo[kc][3]);
        }
    }

    float m = -INFINITY, l = 0.f;  // softmax state for row r
    float acc0[4] = {0.f, 0.f, 0.f, 0.f};   // PV accum, ntile 0
    float acc1[4] = {0.f, 0.f, 0.f, 0.f};   // PV accum, ntile 1

    const unsigned bits = g_bm[h * NB + qi];

    for (int j = 0; j <= qi; ++j) {
        if (!((bits >> j) & 1u)) continue;

        // --- stage K,V tiles (padded rows, coalesced float4) ---
        {
            const float4* kg = reinterpret_cast<const float4*>(k + head_off + (size_t)j * BS * HDIM);
            const float4* vg = reinterpret_cast<const float4*>(v + head_off + (size_t)j * BS * HDIM);
            float4* ks = reinterpret_cast<float4*>(sK);
            float4* vs = reinterpret_cast<float4*>(sV);
            const int i0 = t, i1 = t + 256;
            ks[(i0 >> 4) * (KP / 4) + (i0 & 15)] = kg[i0];
            ks[(i1 >> 4) * (KP / 4) + (i1 & 15)] = kg[i1];
            vs[(i0 >> 4) * (VP / 4) + (i0 & 15)] = vg[i0];
            vs[(i1 >> 4) * (VP / 4) + (i1 & 15)] = vg[i1];
        }
        __syncthreads();

        // --- scores: S(16x8 per warp) = Q(16x64) . K^T, 3-pass tf32 ---
        {
            float sd[4] = {0.f, 0.f, 0.f, 0.f};
            const int krow = 8 * wc + g;              // B col (n) = local k-row
            #pragma unroll
            for (int kc = 0; kc < 8; ++kc) {
                const float b0f = sK[krow * KP + 8 * kc + tg];
                const float b1f = sK[krow * KP + 8 * kc + tg + 4];
                unsigned bh0, bl0, bh1, bl1;
                split_tf32(b0f, bh0, bl0);
                split_tf32(b1f, bh1, bl1);
                mma_tf32(sd, qhi[kc], bh0, bh1);
                mma_tf32(sd, qhi[kc], bl0, bl1);
                mma_tf32(sd, qlo[kc], bh0, bh1);
            }
            const int row0 = 16 * wr + g;
            const int col0 = 8 * wc + 2 * tg;
            sS[row0 * SP + col0]           = sd[0];
            sS[row0 * SP + col0 + 1]       = sd[1];
            sS[(row0 + 8) * SP + col0]     = sd[2];
            sS[(row0 + 8) * SP + col0 + 1] = sd[3];
        }
        __syncthreads();

        // --- softmax (exact fp32, same math as validated SIMT kernel) ---
        {
            float s0 = sS[r * SP + c];
            float s1 = sS[r * SP + c + 8];
            float s2 = sS[r * SP + c + 16];
            float s3 = sS[r * SP + c + 24];
            if (j == qi) {
                if (c      > r) s0 = -INFINITY;
                if (c +  8 > r) s1 = -INFINITY;
                if (c + 16 > r) s2 = -INFINITY;
                if (c + 24 > r) s3 = -INFINITY;
            }
            float ms = fmaxf(fmaxf(s0, s1), fmaxf(s2, s3));
            #pragma unroll
            for (int off = 4; off; off >>= 1)
                ms = fmaxf(ms, __shfl_xor_sync(0xffffffffu, ms, off, 8));

            const float mn    = fmaxf(m, ms);
            const float scale = __expf(m - mn);
            const float p0 = __expf(s0 - mn);
            const float p1 = __expf(s1 - mn);
            const float p2 = __expf(s2 - mn);
            const float p3 = __expf(s3 - mn);

            float lb = p0 + p1 + p2 + p3;
            #pragma unroll
            for (int off = 4; off; off >>= 1)
                lb += __shfl_xor_sync(0xffffffffu, lb, off, 8);

            l = l * scale + lb;
            m = mn;

            unsigned hi, lo;
            split_tf32(p0, hi, lo);
            sPhi[r * PP + c]      = __uint_as_float(hi);  sPlo[r * PP + c]      = __uint_as_float(lo);
            split_tf32(p1, hi, lo);
            sPhi[r * PP + c + 8]  = __uint_as_float(hi);  sPlo[r * PP + c + 8]  = __uint_as_float(lo);
            split_tf32(p2, hi, lo);
            sPhi[r * PP + c + 16] = __uint_as_float(hi);  sPlo[r * PP + c + 16] = __uint_as_float(lo);
            split_tf32(p3, hi, lo);
            sPhi[r * PP + c + 24] = __uint_as_float(hi);  sPlo[r * PP + c + 24] = __uint_as_float(lo);

            if (c == 0) sRow[r] = scale;
        }
        __syncthreads();

        // --- PV: acc(16x16 per warp) += P(16x32) . V(32x64-slice), 3-pass ---
        {
            const float scale0 = sRow[16 * wr + g];
            const float scale1 = sRow[16 * wr + g + 8];
            acc0[0] *= scale0; acc0[1] *= scale0; acc0[2] *= scale1; acc0[3] *= scale1;
            acc1[0] *= scale0; acc1[1] *= scale0; acc1[2] *= scale1; acc1[3] *= scale1;

            const int prow0 = (16 * wr + g) * PP;
            const int prow1 = (16 * wr + g + 8) * PP;
            const int dim0  = 16 * wc + g;     // B col (n) for ntile 0; +8 for ntile 1

            #pragma unroll
            for (int kc = 0; kc < 4; ++kc) {
                const int kcol = 8 * kc + tg;
                unsigned ahi[4], alo[4];
                ahi[0] = __float_as_uint(sPhi[prow0 + kcol]);
                ahi[1] = __float_as_uint(sPhi[prow1 + kcol]);
                ahi[2] = __float_as_uint(sPhi[prow0 + kcol + 4]);
                ahi[3] = __float_as_uint(sPhi[prow1 + kcol + 4]);
                alo[0] = __float_as_uint(sPlo[prow0 + kcol]);
                alo[1] = __float_as_uint(sPlo[prow1 + kcol]);
                alo[2] = __float_as_uint(sPlo[prow0 + kcol + 4]);
                alo[3] = __float_as_uint(sPlo[prow1 + kcol + 4]);

                // ntile 0
                {
                    const float b0f = sV[kcol * VP + dim0];
                    const float b1f = sV[(kcol + 4) * VP + dim0];
                    unsigned bh0, bl0, bh1, bl1;
                    split_tf32(b0f, bh0, bl0);
                    split_tf32(b1f, bh1, bl1);
                    mma_tf32(acc0, ahi, bh0, bh1);
                    mma_tf32(acc0, ahi, bl0, bl1);
                    mma_tf32(acc0, alo, bh0, bh1);
                }
                // ntile 1
                {
                    const float b0f = sV[kcol * VP + dim0 + 8];
                    const float b1f = sV[(kcol + 4) * VP + dim0 + 8];
                    unsigned bh0, bl0, bh1, bl1;
                    split_tf32(b0f, bh0, bl0);
                    split_tf32(b1f, bh1, bl1);
                    mma_tf32(acc1, ahi, bh0, bh1);
                    mma_tf32(acc1, ahi, bl0, bl1);
                    mma_tf32(acc1, alo, bh0, bh1);
                }
            }
        }
        __syncthreads();   // protect sK/sV/sS/sP before next iteration
    }

    // --- epilogue: normalize and store ---
    if (c == 0) sRow[r] = 1.f / l;   // diagonal block guarantees l > 0
    __syncthreads();
    {
        const float invl0 = sRow[16 * wr + g];
        const float invl1 = sRow[16 * wr + g + 8];
        const int row0 = qi * BS + 16 * wr + g;
        const int d0   = 16 * wc + 2 * tg;
        float* o0 = out + head_off + (size_t)row0 * HDIM;
        float* o1 = o0 + 8 * HDIM;

        float2 t0, t1;
        t0.x = acc0[0] * invl0; t0.y = acc0[1] * invl0;
        t1.x = acc0[2] * invl1; t1.y = acc0[3] * invl1;
        *reinterpret_cast<float2*>(o0 + d0) = t0;
        *reinterpret_cast<float2*>(o1 + d0) = t1;
        t0.x = acc1[0] * invl0; t0.y = acc1[1] * invl0;
        t1.x = acc1[2] * invl1; t1.y = acc1[3] * invl1;
        *reinterpret_cast<float2*>(o0 + d0 + 8) = t0;
        *reinterpret_cast<float2*>(o1 + d0 + 8) = t1;
    }
}

// ---------------------------------------------------------------------------
extern "C" void kernel_launch(void* const* d_in, const int* in_sizes, int n_in,
                              void* d_out, int out_size) {
    (void)in_sizes; (void)n_in; (void)out_size;
    const float* q    = (const float*)d_in[0];
    const float* k    = (const float*)d_in[1];
    const float* v    = (const float*)d_in[2];
    const float* mask = (const float*)d_in[3];
    float* out        = (float*)d_out;

    block_mask_kernel<<<dim3(HEADS, NB), 256>>>(mask);
    attn_kernel<<<dim3(NB, BATCH * HEADS), 256>>>(q, k, v, out);
}

// round 6
// speedup vs baseline: 8.1166x; 1.1341x over previous
#include <cuda_runtime.h>
#include <math.h>
#include <stdint.h>

constexpr int BATCH = 8;
constexpr int HEADS = 16;
constexpr int SEQ   = 1024;
constexpr int HDIM  = 64;
constexpr int BS    = 32;
constexpr int NB    = SEQ / BS;

// NOTE: strides are in the array's OWN element units and must be >= row data length.
constexpr int KP2 = 68;  // sK2 row stride in float2; 64 data pairs + pad, LDS.64 conflict-free
constexpr int VPF = 72;  // sV row stride in floats; 64 data + pad, PV B loads conflict-free
constexpr int SP  = 40;  // sS row stride (floats)
constexpr int PP  = 36;  // sP row stride (floats)

__device__ unsigned g_bm[HEADS * NB];

// ---------------------------------------------------------------------------
__global__ void block_mask_kernel(const float* __restrict__ mask) {
    const int h  = blockIdx.x;
    const int bi = blockIdx.y;
    const int t  = threadIdx.x;
    __shared__ unsigned sbits;
    if (t == 0) sbits = 0u;
    __syncthreads();

    const int col = t * 4;
    const float* base = mask + ((size_t)h * SEQ + (size_t)bi * BS) * SEQ;
    bool any = false;
    #pragma unroll 4
    for (int r = 0; r < BS; ++r) {
        float4 vv = *reinterpret_cast<const float4*>(base + (size_t)r * SEQ + col);
        any |= (vv.x != 0.f) | (vv.y != 0.f) | (vv.z != 0.f) | (vv.w != 0.f);
    }
    if (any) atomicOr(&sbits, 1u << (col >> 5));
    __syncthreads();
    if (t == 0) g_bm[h * NB + bi] = sbits | (1u << bi);
}

// ---------------------------------------------------------------------------
__device__ __forceinline__ float f2tf32f(float x) {
    unsigned r;
    asm("cvt.rna.tf32.f32 %0, %1;" : "=r"(r) : "f"(x));
    return __uint_as_float(r);
}
__device__ __forceinline__ void split_tf32(float x, unsigned& hi, unsigned& lo) {
    asm("cvt.rna.tf32.f32 %0, %1;" : "=r"(hi) : "f"(x));
    asm("cvt.rna.tf32.f32 %0, %1;" : "=r"(lo) : "f"(x - __uint_as_float(hi)));
}
__device__ __forceinline__ void mma_tf32(float* d, const unsigned* a, unsigned b0, unsigned b1) {
    asm volatile(
        "mma.sync.aligned.m16n8k8.row.col.f32.tf32.tf32.f32 "
        "{%0,%1,%2,%3},{%4,%5,%6,%7},{%8,%9},{%0,%1,%2,%3};"
        : "+f"(d[0]), "+f"(d[1]), "+f"(d[2]), "+f"(d[3])
        : "r"(a[0]), "r"(a[1]), "r"(a[2]), "r"(a[3]), "r"(b0), "r"(b1));
}

// ---------------------------------------------------------------------------
// Block-sparse causal flash attention, tensor cores.
// QK^T: 3-pass tf32 (fp32-grade scores). PV: single-pass tf32 (rna).
// K pre-split to (hi,lo) at staging; V pre-rounded at staging.
// Grid (NB, BATCH*HEADS), 256 threads = 8 warps.
// ---------------------------------------------------------------------------
__global__ __launch_bounds__(256, 2)
void attn_kernel(const float* __restrict__ q,
                 const float* __restrict__ k,
                 const float* __restrict__ v,
                 float* __restrict__ out) {
    const int qi = blockIdx.x;
    const int bh = blockIdx.y;
    const int h  = bh & (HEADS - 1);
    const int t  = threadIdx.x;
    const int w    = t >> 5;
    const int lane = t & 31;
    const int g  = lane >> 2;      // 0..7
    const int tg = lane & 3;       // 0..3
    const int wr = w >> 2;         // 0..1
    const int wc = w & 3;          // 0..3
    const int r  = t >> 3;         // 0..31 (softmax row)
    const int c  = t & 7;          // 0..7

    __shared__ float2 sK2[BS * KP2];   // (hi,lo) tf32 pairs, 17.4 KB
    __shared__ float  sV [BS * VPF];   // tf32-rounded V
    __shared__ float  sS [BS * SP];
    __shared__ float  sP [BS * PP];    // tf32-rounded probs
    __shared__ float  sRow[BS];

    const size_t head_off = (size_t)bh * SEQ * HDIM;

    // --- Q fragments (hi/lo), once per CTA ---
    unsigned qhi[8][4], qlo[8][4];
    {
        const int row0 = qi * BS + 16 * wr + g;
        const float* q0 = q + head_off + (size_t)row0 * HDIM;
        const float* q1 = q0 + 8 * HDIM;
        #pragma unroll
        for (int kc = 0; kc < 8; ++kc) {
            const int c0 = 8 * kc + tg;
            split_tf32(q0[c0],     qhi[kc][0], qlo[kc][0]);
            split_tf32(q1[c0],     qhi[kc][1], qlo[kc][1]);
            split_tf32(q0[c0 + 4], qhi[kc][2], qlo[kc][2]);
            split_tf32(q1[c0 + 4], qhi[kc][3], qlo[kc][3]);
        }
    }

    float m = -INFINITY, l = 0.f;
    float acc0[4] = {0.f, 0.f, 0.f, 0.f};
    float acc1[4] = {0.f, 0.f, 0.f, 0.f};

    const unsigned bits = g_bm[h * NB + qi];

    const int srow0 = t >> 4,         scol0 = 4 * (t & 15);
    const int srow1 = (t + 256) >> 4, scol1 = 4 * ((t + 256) & 15);

    for (int j = 0; j <= qi; ++j) {
        if (!((bits >> j) & 1u)) continue;

        // --- stage K (split hi/lo) and V (rounded) ---
        {
            const float* kg = k + head_off + (size_t)j * BS * HDIM;
            const float* vg = v + head_off + (size_t)j * BS * HDIM;
            #pragma unroll
            for (int part = 0; part < 2; ++part) {
                const int row = part ? srow1 : srow0;
                const int col = part ? scol1 : scol0;
                float4 kv = *reinterpret_cast<const float4*>(kg + row * HDIM + col);
                unsigned h0, l0, h1, l1, h2, l2, h3, l3;
                split_tf32(kv.x, h0, l0); split_tf32(kv.y, h1, l1);
                split_tf32(kv.z, h2, l2); split_tf32(kv.w, h3, l3);
                float4* dst = reinterpret_cast<float4*>(&sK2[row * KP2 + col]);
                dst[0] = make_float4(__uint_as_float(h0), __uint_as_float(l0),
                                     __uint_as_float(h1), __uint_as_float(l1));
                dst[1] = make_float4(__uint_as_float(h2), __uint_as_float(l2),
                                     __uint_as_float(h3), __uint_as_float(l3));

                float4 vv = *reinterpret_cast<const float4*>(vg + row * HDIM + col);
                vv.x = f2tf32f(vv.x); vv.y = f2tf32f(vv.y);
                vv.z = f2tf32f(vv.z); vv.w = f2tf32f(vv.w);
                *reinterpret_cast<float4*>(&sV[row * VPF + col]) = vv;
            }
        }
        __syncthreads();

        // --- scores: 3-pass tf32 (hi*hi + hi*lo + lo*hi) ---
        {
            float sd[4] = {0.f, 0.f, 0.f, 0.f};
            const int krow = 8 * wc + g;
            const float2* kb = &sK2[krow * KP2];
            #pragma unroll
            for (int kc = 0; kc < 8; ++kc) {
                const float2 e0 = kb[8 * kc + tg];
                const float2 e1 = kb[8 * kc + tg + 4];
                const unsigned bh0 = __float_as_uint(e0.x), bl0 = __float_as_uint(e0.y);
                const unsigned bh1 = __float_as_uint(e1.x), bl1 = __float_as_uint(e1.y);
                mma_tf32(sd, qhi[kc], bh0, bh1);
                mma_tf32(sd, qhi[kc], bl0, bl1);
                mma_tf32(sd, qlo[kc], bh0, bh1);
            }
            const int row0 = 16 * wr + g;
            const int col0 = 8 * wc + 2 * tg;
            sS[row0 * SP + col0]           = sd[0];
            sS[row0 * SP + col0 + 1]       = sd[1];
            sS[(row0 + 8) * SP + col0]     = sd[2];
            sS[(row0 + 8) * SP + col0 + 1] = sd[3];
        }
        __syncthreads();

        // --- softmax (exact fp32) ---
        {
            float s0 = sS[r * SP + c];
            float s1 = sS[r * SP + c + 8];
            float s2 = sS[r * SP + c + 16];
            float s3 = sS[r * SP + c + 24];
            if (j == qi) {
                if (c      > r) s0 = -INFINITY;
                if (c +  8 > r) s1 = -INFINITY;
                if (c + 16 > r) s2 = -INFINITY;
                if (c + 24 > r) s3 = -INFINITY;
            }
            float ms = fmaxf(fmaxf(s0, s1), fmaxf(s2, s3));
            #pragma unroll
            for (int off = 4; off; off >>= 1)
                ms = fmaxf(ms, __shfl_xor_sync(0xffffffffu, ms, off, 8));

            const float mn    = fmaxf(m, ms);
            const float scale = __expf(m - mn);
            const float p0 = __expf(s0 - mn);
            const float p1 = __expf(s1 - mn);
            const float p2 = __expf(s2 - mn);
            const float p3 = __expf(s3 - mn);

            float lb = p0 + p1 + p2 + p3;
            #pragma unroll
            for (int off = 4; off; off >>= 1)
                lb += __shfl_xor_sync(0xffffffffu, lb, off, 8);

            l = l * scale + lb;
            m = mn;

            sP[r * PP + c]      = f2tf32f(p0);
            sP[r * PP + c + 8]  = f2tf32f(p1);
            sP[r * PP + c + 16] = f2tf32f(p2);
            sP[r * PP + c + 24] = f2tf32f(p3);
            if (c == 0) sRow[r] = scale;
        }
        __syncthreads();

        // --- PV: single-pass tf32 ---
        {
            const float scale0 = sRow[16 * wr + g];
            const float scale1 = sRow[16 * wr + g + 8];
            acc0[0] *= scale0; acc0[1] *= scale0; acc0[2] *= scale1; acc0[3] *= scale1;
            acc1[0] *= scale0; acc1[1] *= scale0; acc1[2] *= scale1; acc1[3] *= scale1;

            const int prow0 = (16 * wr + g) * PP;
            const int prow1 = (16 * wr + g + 8) * PP;
            const int dim0  = 16 * wc + g;

            #pragma unroll
            for (int kc = 0; kc < 4; ++kc) {
                const int kcol = 8 * kc + tg;
                unsigned a[4];
                a[0] = __float_as_uint(sP[prow0 + kcol]);
                a[1] = __float_as_uint(sP[prow1 + kcol]);
                a[2] = __float_as_uint(sP[prow0 + kcol + 4]);
                a[3] = __float_as_uint(sP[prow1 + kcol + 4]);

                const unsigned b00 = __float_as_uint(sV[kcol * VPF + dim0]);
                const unsigned b01 = __float_as_uint(sV[(kcol + 4) * VPF + dim0]);
                mma_tf32(acc0, a, b00, b01);

                const unsigned b10 = __float_as_uint(sV[kcol * VPF + dim0 + 8]);
                const unsigned b11 = __float_as_uint(sV[(kcol + 4) * VPF + dim0 + 8]);
                mma_tf32(acc1, a, b10, b11);
            }
        }
        __syncthreads();
    }

    // --- epilogue ---
    if (c == 0) sRow[r] = 1.f / l;
    __syncthreads();
    {
        const float invl0 = sRow[16 * wr + g];
        const float invl1 = sRow[16 * wr + g + 8];
        const int row0 = qi * BS + 16 * wr + g;
        const int d0   = 16 * wc + 2 * tg;
        float* o0 = out + head_off + (size_t)row0 * HDIM;
        float* o1 = o0 + 8 * HDIM;

        float2 t0, t1;
        t0.x = acc0[0] * invl0; t0.y = acc0[1] * invl0;
        t1.x = acc0[2] * invl1; t1.y = acc0[3] * invl1;
        *reinterpret_cast<float2*>(o0 + d0) = t0;
        *reinterpret_cast<float2*>(o1 + d0) = t1;
        t0.x = acc1[0] * invl0; t0.y = acc1[1] * invl0;
        t1.x = acc1[2] * invl1; t1.y = acc1[3] * invl1;
        *reinterpret_cast<float2*>(o0 + d0 + 8) = t0;
        *reinterpret_cast<float2*>(o1 + d0 + 8) = t1;
    }
}

// ---------------------------------------------------------------------------
extern "C" void kernel_launch(void* const* d_in, const int* in_sizes, int n_in,
                              void* d_out, int out_size) {
    (void)in_sizes; (void)n_in; (void)out_size;
    const float* q    = (const float*)d_in[0];
    const float* k    = (const float*)d_in[1];
    const float* v    = (const float*)d_in[2];
    const float* mask = (const float*)d_in[3];
    float* out        = (float*)d_out;

    block_mask_kernel<<<dim3(HEADS, NB), 256>>>(mask);
    attn_kernel<<<dim3(NB, BATCH * HEADS), 256>>>(q, k, v, out);
}

// round 7
// speedup vs baseline: 8.5630x; 1.0550x over previous
#include <cuda_runtime.h>
#include <math.h>
#include <stdint.h>

constexpr int BATCH = 8;
constexpr int HEADS = 16;
constexpr int SEQ   = 1024;
constexpr int HDIM  = 64;
constexpr int BS    = 32;
constexpr int NB    = SEQ / BS;

// Strides in the array's OWN element units; must be >= row data length (64).
constexpr int KP2 = 68;  // K tile row stride in float2 (hi,lo)
constexpr int VPF = 72;  // V tile row stride in floats
constexpr int SP  = 40;  // score row stride (floats)
constexpr int PP  = 36;  // probs row stride (floats)

constexpr int KTILE_B = BS * KP2 * 8;  // 17408 bytes per K tile
constexpr int VTILE_B = BS * VPF * 4;  // 9216 bytes per V tile

__device__ unsigned g_bm[HEADS * NB];
// Preprocessed tiles, already in padded smem layout (copied verbatim).
__device__ float2 g_Ksp[(size_t)BATCH * HEADS * NB * BS * KP2];  // ~71 MB
__device__ float  g_Vtf[(size_t)BATCH * HEADS * NB * BS * VPF];  // ~38 MB

// ---------------------------------------------------------------------------
__global__ void block_mask_kernel(const float* __restrict__ mask) {
    const int h  = blockIdx.x;
    const int bi = blockIdx.y;
    const int t  = threadIdx.x;
    __shared__ unsigned sbits;
    if (t == 0) sbits = 0u;
    __syncthreads();

    const int col = t * 4;
    const float* base = mask + ((size_t)h * SEQ + (size_t)bi * BS) * SEQ;
    bool any = false;
    #pragma unroll 4
    for (int r = 0; r < BS; ++r) {
        float4 vv = *reinterpret_cast<const float4*>(base + (size_t)r * SEQ + col);
        any |= (vv.x != 0.f) | (vv.y != 0.f) | (vv.z != 0.f) | (vv.w != 0.f);
    }
    if (any) atomicOr(&sbits, 1u << (col >> 5));
    __syncthreads();
    if (t == 0) g_bm[h * NB + bi] = sbits | (1u << bi);
}

// ---------------------------------------------------------------------------
__device__ __forceinline__ float f2tf32f(float x) {
    unsigned r;
    asm("cvt.rna.tf32.f32 %0, %1;" : "=r"(r) : "f"(x));
    return __uint_as_float(r);
}
__device__ __forceinline__ void split_tf32(float x, unsigned& hi, unsigned& lo) {
    asm("cvt.rna.tf32.f32 %0, %1;" : "=r"(hi) : "f"(x));
    asm("cvt.rna.tf32.f32 %0, %1;" : "=r"(lo) : "f"(x - __uint_as_float(hi)));
}
__device__ __forceinline__ void mma_tf32(float* d, const unsigned* a, unsigned b0, unsigned b1) {
    asm volatile(
        "mma.sync.aligned.m16n8k8.row.col.f32.tf32.tf32.f32 "
        "{%0,%1,%2,%3},{%4,%5,%6,%7},{%8,%9},{%0,%1,%2,%3};"
        : "+f"(d[0]), "+f"(d[1]), "+f"(d[2]), "+f"(d[3])
        : "r"(a[0]), "r"(a[1]), "r"(a[2]), "r"(a[3]), "r"(b0), "r"(b1));
}
__device__ __forceinline__ void cp_async16(unsigned s, const void* g) {
    asm volatile("cp.async.cg.shared.global [%0], [%1], 16;" :: "r"(s), "l"(g));
}

// ---------------------------------------------------------------------------
// Preprocess: split K to (hi,lo) tf32 pairs, round V to tf32, write in padded
// tile layout. One tile per CTA. Grid (NB, BATCH*HEADS), 256 threads.
// ---------------------------------------------------------------------------
__global__ void prep_kernel(const float* __restrict__ k, const float* __restrict__ v) {
    const int j  = blockIdx.x;
    const int bh = blockIdx.y;
    const int t  = threadIdx.x;

    const float* kg = k + ((size_t)bh * SEQ + (size_t)j * BS) * HDIM;
    const float* vg = v + ((size_t)bh * SEQ + (size_t)j * BS) * HDIM;
    float2* kd = g_Ksp + ((size_t)bh * NB + j) * BS * KP2;
    float*  vd = g_Vtf + ((size_t)bh * NB + j) * BS * VPF;

    #pragma unroll
    for (int part = 0; part < 2; ++part) {
        const int idx = t + part * 256;         // 0..511 elems of 32x16 float4s
        const int row = idx >> 4;
        const int col = 4 * (idx & 15);
        float4 kv = *reinterpret_cast<const float4*>(kg + row * HDIM + col);
        unsigned h0, l0, h1, l1, h2, l2, h3, l3;
        split_tf32(kv.x, h0, l0); split_tf32(kv.y, h1, l1);
        split_tf32(kv.z, h2, l2); split_tf32(kv.w, h3, l3);
        float4* dst = reinterpret_cast<float4*>(&kd[row * KP2 + col]);
        dst[0] = make_float4(__uint_as_float(h0), __uint_as_float(l0),
                             __uint_as_float(h1), __uint_as_float(l1));
        dst[1] = make_float4(__uint_as_float(h2), __uint_as_float(l2),
                             __uint_as_float(h3), __uint_as_float(l3));

        float4 vv = *reinterpret_cast<const float4*>(vg + row * HDIM + col);
        vv.x = f2tf32f(vv.x); vv.y = f2tf32f(vv.y);
        vv.z = f2tf32f(vv.z); vv.w = f2tf32f(vv.w);
        *reinterpret_cast<float4*>(&vd[row * VPF + col]) = vv;
    }
}

// ---------------------------------------------------------------------------
// Block-sparse causal flash attention, tensor cores, cp.async double-buffered.
// QK^T: 3-pass tf32. PV: single-pass tf32. Grid (NB, BATCH*HEADS), 256 thr.
// ---------------------------------------------------------------------------
__global__ __launch_bounds__(256, 2)
void attn_kernel(const float* __restrict__ q, float* __restrict__ out) {
    const int qi = blockIdx.x;
    const int bh = blockIdx.y;
    const int h  = bh & (HEADS - 1);
    const int t  = threadIdx.x;
    const int w    = t >> 5;
    const int lane = t & 31;
    const int g  = lane >> 2;
    const int tg = lane & 3;
    const int wr = w >> 2;
    const int wc = w & 3;
    const int r  = t >> 3;
    const int c  = t & 7;

    extern __shared__ char smem[];
    float2* sK2base = reinterpret_cast<float2*>(smem);                 // [2][BS*KP2]
    float*  sVbase  = reinterpret_cast<float*>(smem + 2 * KTILE_B);    // [2][BS*VPF]
    float*  sS      = sVbase + 2 * BS * VPF;
    float*  sP      = sS + BS * SP;
    float*  sRow    = sP + BS * PP;

    const size_t head_off = (size_t)bh * SEQ * HDIM;

    // --- Q fragments (hi/lo), once per CTA ---
    unsigned qhi[8][4], qlo[8][4];
    {
        const int row0 = qi * BS + 16 * wr + g;
        const float* q0 = q + head_off + (size_t)row0 * HDIM;
        const float* q1 = q0 + 8 * HDIM;
        #pragma unroll
        for (int kc = 0; kc < 8; ++kc) {
            const int c0 = 8 * kc + tg;
            split_tf32(q0[c0],     qhi[kc][0], qlo[kc][0]);
            split_tf32(q1[c0],     qhi[kc][1], qlo[kc][1]);
            split_tf32(q0[c0 + 4], qhi[kc][2], qlo[kc][2]);
            split_tf32(q1[c0 + 4], qhi[kc][3], qlo[kc][3]);
        }
    }

    float m = -INFINITY, l = 0.f;
    float acc0[4] = {0.f, 0.f, 0.f, 0.f};
    float acc1[4] = {0.f, 0.f, 0.f, 0.f};

    // Active-j bitmask restricted to j <= qi (diagonal bit always set).
    unsigned rem = g_bm[h * NB + qi] & (unsigned)((2ull << qi) - 1ull);

    const char* ktiles = reinterpret_cast<const char*>(g_Ksp + (size_t)bh * NB * BS * KP2);
    const char* vtiles = reinterpret_cast<const char*>(g_Vtf + (size_t)bh * NB * BS * VPF);

    // stage tile j into buffer b (all 256 threads participate)
    auto stage = [&](int b, int j) {
        const char* gk = ktiles + (size_t)j * KTILE_B;
        const char* gv = vtiles + (size_t)j * VTILE_B;
        unsigned sk = (unsigned)__cvta_generic_to_shared(smem) + b * KTILE_B;
        unsigned sv = (unsigned)__cvta_generic_to_shared(smem) + 2 * KTILE_B + b * VTILE_B;
        #pragma unroll
        for (int ofs = 0; ofs < KTILE_B; ofs += 4096) {
            const int o = ofs + t * 16;
            if (o < KTILE_B) cp_async16(sk + o, gk + o);
        }
        #pragma unroll
        for (int ofs = 0; ofs < VTILE_B; ofs += 4096) {
            const int o = ofs + t * 16;
            if (o < VTILE_B) cp_async16(sv + o, gv + o);
        }
        asm volatile("cp.async.commit_group;");
    };

    int jcur = __ffs(rem) - 1;       // at least the diagonal bit is set
    rem &= rem - 1;
    stage(0, jcur);
    int cur = 0;

    while (jcur >= 0) {
        int jnext = -1;
        if (rem) { jnext = __ffs(rem) - 1; rem &= rem - 1; }
        if (jnext >= 0) {
            stage(cur ^ 1, jnext);
            asm volatile("cp.async.wait_group 1;");
        } else {
            asm volatile("cp.async.wait_group 0;");
        }
        __syncthreads();   // tile(cur) visible to all threads

        const float2* sK2 = sK2base + cur * BS * KP2;
        const float*  sV  = sVbase  + cur * BS * VPF;

        // --- scores: 3-pass tf32 ---
        {
            float sd[4] = {0.f, 0.f, 0.f, 0.f};
            const int krow = 8 * wc + g;
            const float2* kb = &sK2[krow * KP2];
            #pragma unroll
            for (int kc = 0; kc < 8; ++kc) {
                const float2 e0 = kb[8 * kc + tg];
                const float2 e1 = kb[8 * kc + tg + 4];
                const unsigned bh0 = __float_as_uint(e0.x), bl0 = __float_as_uint(e0.y);
                const unsigned bh1 = __float_as_uint(e1.x), bl1 = __float_as_uint(e1.y);
                mma_tf32(sd, qhi[kc], bh0, bh1);
                mma_tf32(sd, qhi[kc], bl0, bl1);
                mma_tf32(sd, qlo[kc], bh0, bh1);
            }
            const int row0 = 16 * wr + g;
            const int col0 = 8 * wc + 2 * tg;
            sS[row0 * SP + col0]           = sd[0];
            sS[row0 * SP + col0 + 1]       = sd[1];
            sS[(row0 + 8) * SP + col0]     = sd[2];
            sS[(row0 + 8) * SP + col0 + 1] = sd[3];
        }
        __syncthreads();

        // --- softmax (exact fp32) ---
        {
            float s0 = sS[r * SP + c];
            float s1 = sS[r * SP + c + 8];
            float s2 = sS[r * SP + c + 16];
            float s3 = sS[r * SP + c + 24];
            if (jcur == qi) {
                if (c      > r) s0 = -INFINITY;
                if (c +  8 > r) s1 = -INFINITY;
                if (c + 16 > r) s2 = -INFINITY;
                if (c + 24 > r) s3 = -INFINITY;
            }
            float ms = fmaxf(fmaxf(s0, s1), fmaxf(s2, s3));
            #pragma unroll
            for (int off = 4; off; off >>= 1)
                ms = fmaxf(ms, __shfl_xor_sync(0xffffffffu, ms, off, 8));

            const float mn    = fmaxf(m, ms);
            const float scale = __expf(m - mn);
            const float p0 = __expf(s0 - mn);
            const float p1 = __expf(s1 - mn);
            const float p2 = __expf(s2 - mn);
            const float p3 = __expf(s3 - mn);

            float lb = p0 + p1 + p2 + p3;
            #pragma unroll
            for (int off = 4; off; off >>= 1)
                lb += __shfl_xor_sync(0xffffffffu, lb, off, 8);

            l = l * scale + lb;
            m = mn;

            sP[r * PP + c]      = f2tf32f(p0);
            sP[r * PP + c + 8]  = f2tf32f(p1);
            sP[r * PP + c + 16] = f2tf32f(p2);
            sP[r * PP + c + 24] = f2tf32f(p3);
            if (c == 0) sRow[r] = scale;
        }
        __syncthreads();

        // --- PV: single-pass tf32 ---
        {
            const float scale0 = sRow[16 * wr + g];
            const float scale1 = sRow[16 * wr + g + 8];
            acc0[0] *= scale0; acc0[1] *= scale0; acc0[2] *= scale1; acc0[3] *= scale1;
            acc1[0] *= scale0; acc1[1] *= scale0; acc1[2] *= scale1; acc1[3] *= scale1;

            const int prow0 = (16 * wr + g) * PP;
            const int prow1 = (16 * wr + g + 8) * PP;
            const int dim0  = 16 * wc + g;

            #pragma unroll
            for (int kc = 0; kc < 4; ++kc) {
                const int kcol = 8 * kc + tg;
                unsigned a[4];
                a[0] = __float_as_uint(sP[prow0 + kcol]);
                a[1] = __float_as_uint(sP[prow1 + kcol]);
                a[2] = __float_as_uint(sP[prow0 + kcol + 4]);
                a[3] = __float_as_uint(sP[prow1 + kcol + 4]);

                const unsigned b00 = __float_as_uint(sV[kcol * VPF + dim0]);
                const unsigned b01 = __float_as_uint(sV[(kcol + 4) * VPF + dim0]);
                mma_tf32(acc0, a, b00, b01);

                const unsigned b10 = __float_as_uint(sV[kcol * VPF + dim0 + 8]);
                const unsigned b11 = __float_as_uint(sV[(kcol + 4) * VPF + dim0 + 8]);
                mma_tf32(acc1, a, b10, b11);
            }
        }
        __syncthreads();   // all reads of tile(cur), sS, sP done

        jcur = jnext;
        cur ^= 1;
    }

    // --- epilogue ---
    if (c == 0) sRow[r] = 1.f / l;
    __syncthreads();
    {
        const float invl0 = sRow[16 * wr + g];
        const float invl1 = sRow[16 * wr + g + 8];
        const int row0 = qi * BS + 16 * wr + g;
        const int d0   = 16 * wc + 2 * tg;
        float* o0 = out + head_off + (size_t)row0 * HDIM;
        float* o1 = o0 + 8 * HDIM;

        float2 t0, t1;
        t0.x = acc0[0] * invl0; t0.y = acc0[1] * invl0;
        t1.x = acc0[2] * invl1; t1.y = acc0[3] * invl1;
        *reinterpret_cast<float2*>(o0 + d0) = t0;
        *reinterpret_cast<float2*>(o1 + d0) = t1;
        t0.x = acc1[0] * invl0; t0.y = acc1[1] * invl0;
        t1.x = acc1[2] * invl1; t1.y = acc1[3] * invl1;
        *reinterpret_cast<float2*>(o0 + d0 + 8) = t0;
        *reinterpret_cast<float2*>(o1 + d0 + 8) = t1;
    }
}

// ---------------------------------------------------------------------------
extern "C" void kernel_launch(void* const* d_in, const int* in_sizes, int n_in,
                              void* d_out, int out_size) {
    (void)in_sizes; (void)n_in; (void)out_size;
    const float* q    = (const float*)d_in[0];
    const float* k    = (const float*)d_in[1];
    const float* v    = (const float*)d_in[2];
    const float* mask = (const float*)d_in[3];
    float* out        = (float*)d_out;

    const int smem_bytes = 2 * KTILE_B + 2 * VTILE_B + (BS * SP + BS * PP + BS) * 4;
    static bool attr_set = false;
    if (!attr_set) {
        cudaFuncSetAttribute(attn_kernel, cudaFuncAttributeMaxDynamicSharedMemorySize, smem_bytes);
        attr_set = true;
    }

    block_mask_kernel<<<dim3(HEADS, NB), 256>>>(mask);
    prep_kernel<<<dim3(NB, BATCH * HEADS), 256>>>(k, v);
    attn_kernel<<<dim3(NB, BATCH * HEADS), 256, smem_bytes>>>(q, out);
}

// round 8
// speedup vs baseline: 9.6893x; 1.1315x over previous
#include <cuda_runtime.h>
#include <math.h>
#include <stdint.h>

constexpr int BATCH = 8;
constexpr int HEADS = 16;
constexpr int SEQ   = 1024;
constexpr int HDIM  = 64;
constexpr int BS    = 32;
constexpr int NB    = SEQ / BS;

// Strides in the array's OWN element units; must be >= row data length (64).
constexpr int KP2 = 68;  // K tile row stride in float2 (hi,lo)
constexpr int VPF = 72;  // V tile row stride in floats
constexpr int SP  = 40;  // score row stride (floats)
constexpr int PP  = 36;  // probs row stride (floats)

constexpr int KTILE_B = BS * KP2 * 8;  // 17408 bytes per K tile
constexpr int VTILE_B = BS * VPF * 4;  // 9216 bytes per V smem tile

__device__ unsigned g_bm[HEADS * NB];
__device__ float2 g_Ksp[(size_t)BATCH * HEADS * NB * BS * KP2];  // pre-split K tiles

// ---------------------------------------------------------------------------
// Mask kernel: the reference mask is block-constant (broadcast of the block
// mask), so one element per 32x32 block decides the block. 1 CTA per head.
// ---------------------------------------------------------------------------
__global__ void block_mask_kernel(const float* __restrict__ mask) {
    const int h  = blockIdx.x;
    const int t  = threadIdx.x;      // 0..1023
    const int bi = t >> 5;           // q-block row
    const int bj = t & 31;           // k-block col
    const float val = mask[((size_t)h * SEQ + (size_t)bi * BS) * SEQ + (size_t)bj * BS];
    const unsigned bits = __ballot_sync(0xffffffffu, val != 0.f);
    if (bj == 0) g_bm[h * NB + bi] = bits | (1u << bi);   // diagonal always on
}

// ---------------------------------------------------------------------------
__device__ __forceinline__ float f2tf32f(float x) {
    unsigned r;
    asm("cvt.rna.tf32.f32 %0, %1;" : "=r"(r) : "f"(x));
    return __uint_as_float(r);
}
__device__ __forceinline__ void split_tf32(float x, unsigned& hi, unsigned& lo) {
    asm("cvt.rna.tf32.f32 %0, %1;" : "=r"(hi) : "f"(x));
    asm("cvt.rna.tf32.f32 %0, %1;" : "=r"(lo) : "f"(x - __uint_as_float(hi)));
}
__device__ __forceinline__ void mma_tf32(float* d, const unsigned* a, unsigned b0, unsigned b1) {
    asm volatile(
        "mma.sync.aligned.m16n8k8.row.col.f32.tf32.tf32.f32 "
        "{%0,%1,%2,%3},{%4,%5,%6,%7},{%8,%9},{%0,%1,%2,%3};"
        : "+f"(d[0]), "+f"(d[1]), "+f"(d[2]), "+f"(d[3])
        : "r"(a[0]), "r"(a[1]), "r"(a[2]), "r"(a[3]), "r"(b0), "r"(b1));
}
__device__ __forceinline__ void cp_async16(unsigned s, const void* g) {
    asm volatile("cp.async.cg.shared.global [%0], [%1], 16;" :: "r"(s), "l"(g));
}

// ---------------------------------------------------------------------------
// Preprocess: split K to (hi,lo) tf32 pairs in padded tile layout. K only.
// ---------------------------------------------------------------------------
__global__ void prep_kernel(const float* __restrict__ k) {
    const int j  = blockIdx.x;
    const int bh = blockIdx.y;
    const int t  = threadIdx.x;

    const float* kg = k + ((size_t)bh * SEQ + (size_t)j * BS) * HDIM;
    float2* kd = g_Ksp + ((size_t)bh * NB + j) * BS * KP2;

    #pragma unroll
    for (int part = 0; part < 2; ++part) {
        const int idx = t + part * 256;
        const int row = idx >> 4;
        const int col = 4 * (idx & 15);
        float4 kv = *reinterpret_cast<const float4*>(kg + row * HDIM + col);
        unsigned h0, l0, h1, l1, h2, l2, h3, l3;
        split_tf32(kv.x, h0, l0); split_tf32(kv.y, h1, l1);
        split_tf32(kv.z, h2, l2); split_tf32(kv.w, h3, l3);
        float4* dst = reinterpret_cast<float4*>(&kd[row * KP2 + col]);
        dst[0] = make_float4(__uint_as_float(h0), __uint_as_float(l0),
                             __uint_as_float(h1), __uint_as_float(l1));
        dst[1] = make_float4(__uint_as_float(h2), __uint_as_float(l2),
                             __uint_as_float(h3), __uint_as_float(l3));
    }
}

// ---------------------------------------------------------------------------
// Block-sparse causal flash attention. QK^T: 3-pass tf32 with 3 independent
// mma accumulator chains. PV: single-pass tf32 (V raw fp32 -> HW tf32 trunc).
// cp.async double-buffered tiles. Grid (NB, BATCH*HEADS), 256 threads.
// ---------------------------------------------------------------------------
__global__ __launch_bounds__(256, 2)
void attn_kernel(const float* __restrict__ q,
                 const float* __restrict__ v,
                 float* __restrict__ out) {
    const int qi = blockIdx.x;
    const int bh = blockIdx.y;
    const int h  = bh & (HEADS - 1);
    const int t  = threadIdx.x;
    const int w    = t >> 5;
    const int lane = t & 31;
    const int g  = lane >> 2;
    const int tg = lane & 3;
    const int wr = w >> 2;
    const int wc = w & 3;
    const int r  = t >> 3;
    const int c  = t & 7;

    extern __shared__ char smem[];
    float2* sK2base = reinterpret_cast<float2*>(smem);                 // [2][BS*KP2]
    float*  sVbase  = reinterpret_cast<float*>(smem + 2 * KTILE_B);    // [2][BS*VPF]
    float*  sS      = sVbase + 2 * BS * VPF;
    float*  sP      = sS + BS * SP;
    float*  sRow    = sP + BS * PP;

    const size_t head_off = (size_t)bh * SEQ * HDIM;

    // --- Q fragments (hi/lo), once per CTA ---
    unsigned qhi[8][4], qlo[8][4];
    {
        const int row0 = qi * BS + 16 * wr + g;
        const float* q0 = q + head_off + (size_t)row0 * HDIM;
        const float* q1 = q0 + 8 * HDIM;
        #pragma unroll
        for (int kc = 0; kc < 8; ++kc) {
            const int c0 = 8 * kc + tg;
            split_tf32(q0[c0],     qhi[kc][0], qlo[kc][0]);
            split_tf32(q1[c0],     qhi[kc][1], qlo[kc][1]);
            split_tf32(q0[c0 + 4], qhi[kc][2], qlo[kc][2]);
            split_tf32(q1[c0 + 4], qhi[kc][3], qlo[kc][3]);
        }
    }

    float m = -INFINITY, l = 0.f;
    float acc0[4] = {0.f, 0.f, 0.f, 0.f};
    float acc1[4] = {0.f, 0.f, 0.f, 0.f};

    unsigned rem = g_bm[h * NB + qi] & (unsigned)((2ull << qi) - 1ull);

    const char* ktiles = reinterpret_cast<const char*>(g_Ksp + (size_t)bh * NB * BS * KP2);
    const char* vsrc   = reinterpret_cast<const char*>(v + head_off);

    auto stage = [&](int b, int j) {
        // K tile: verbatim copy of pre-split padded tile
        const char* gk = ktiles + (size_t)j * KTILE_B;
        unsigned sk = (unsigned)__cvta_generic_to_shared(smem) + b * KTILE_B;
        #pragma unroll
        for (int ofs = 0; ofs < KTILE_B; ofs += 4096) {
            const int o = ofs + t * 16;
            if (o < KTILE_B) cp_async16(sk + o, gk + o);
        }
        // V tile: from original fp32 tensor, row-padded into smem
        const char* gv = vsrc + (size_t)j * BS * HDIM * 4;
        unsigned sv = (unsigned)__cvta_generic_to_shared(smem) + 2 * KTILE_B + b * VTILE_B;
        #pragma unroll
        for (int part = 0; part < 2; ++part) {
            const int idx = t + part * 256;      // 512 chunks of 16B
            const int row = idx >> 4;
            const int col = idx & 15;
            cp_async16(sv + row * (VPF * 4) + col * 16, gv + row * 256 + col * 16);
        }
        asm volatile("cp.async.commit_group;");
    };

    int jcur = __ffs(rem) - 1;
    rem &= rem - 1;
    stage(0, jcur);
    int cur = 0;

    while (jcur >= 0) {
        int jnext = -1;
        if (rem) { jnext = __ffs(rem) - 1; rem &= rem - 1; }
        if (jnext >= 0) {
            stage(cur ^ 1, jnext);
            asm volatile("cp.async.wait_group 1;");
        } else {
            asm volatile("cp.async.wait_group 0;");
        }
        __syncthreads();

        const float2* sK2 = sK2base + cur * BS * KP2;
        const float*  sV  = sVbase  + cur * BS * VPF;

        // --- scores: 3-pass tf32, 3 independent accumulator chains ---
        {
            float sa[4] = {0.f, 0.f, 0.f, 0.f};
            float sb[4] = {0.f, 0.f, 0.f, 0.f};
            float sc[4] = {0.f, 0.f, 0.f, 0.f};
            const int krow = 8 * wc + g;
            const float2* kb = &sK2[krow * KP2];
            #pragma unroll
            for (int kc = 0; kc < 8; ++kc) {
                const float2 e0 = kb[8 * kc + tg];
                const float2 e1 = kb[8 * kc + tg + 4];
                const unsigned bh0 = __float_as_uint(e0.x), bl0 = __float_as_uint(e0.y);
                const unsigned bh1 = __float_as_uint(e1.x), bl1 = __float_as_uint(e1.y);
                mma_tf32(sa, qhi[kc], bh0, bh1);
                mma_tf32(sb, qhi[kc], bl0, bl1);
                mma_tf32(sc, qlo[kc], bh0, bh1);
            }
            const int row0 = 16 * wr + g;
            const int col0 = 8 * wc + 2 * tg;
            sS[row0 * SP + col0]           = sa[0] + (sb[0] + sc[0]);
            sS[row0 * SP + col0 + 1]       = sa[1] + (sb[1] + sc[1]);
            sS[(row0 + 8) * SP + col0]     = sa[2] + (sb[2] + sc[2]);
            sS[(row0 + 8) * SP + col0 + 1] = sa[3] + (sb[3] + sc[3]);
        }
        __syncthreads();

        // --- softmax (exact fp32) ---
        {
            float s0 = sS[r * SP + c];
            float s1 = sS[r * SP + c + 8];
            float s2 = sS[r * SP + c + 16];
            float s3 = sS[r * SP + c + 24];
            if (jcur == qi) {
                if (c      > r) s0 = -INFINITY;
                if (c +  8 > r) s1 = -INFINITY;
                if (c + 16 > r) s2 = -INFINITY;
                if (c + 24 > r) s3 = -INFINITY;
            }
            float ms = fmaxf(fmaxf(s0, s1), fmaxf(s2, s3));
            #pragma unroll
            for (int off = 4; off; off >>= 1)
                ms = fmaxf(ms, __shfl_xor_sync(0xffffffffu, ms, off, 8));

            const float mn    = fmaxf(m, ms);
            const float scale = __expf(m - mn);
            const float p0 = __expf(s0 - mn);
            const float p1 = __expf(s1 - mn);
            const float p2 = __expf(s2 - mn);
            const float p3 = __expf(s3 - mn);

            float lb = p0 + p1 + p2 + p3;
            #pragma unroll
            for (int off = 4; off; off >>= 1)
                lb += __shfl_xor_sync(0xffffffffu, lb, off, 8);

            l = l * scale + lb;
            m = mn;

            sP[r * PP + c]      = f2tf32f(p0);
            sP[r * PP + c + 8]  = f2tf32f(p1);
            sP[r * PP + c + 16] = f2tf32f(p2);
            sP[r * PP + c + 24] = f2tf32f(p3);
            if (c == 0) sRow[r] = scale;
        }
        __syncthreads();

        // --- PV: single-pass tf32 (V raw fp32 bits; HW truncates to tf32) ---
        {
            const float scale0 = sRow[16 * wr + g];
            const float scale1 = sRow[16 * wr + g + 8];
            acc0[0] *= scale0; acc0[1] *= scale0; acc0[2] *= scale1; acc0[3] *= scale1;
            acc1[0] *= scale0; acc1[1] *= scale0; acc1[2] *= scale1; acc1[3] *= scale1;

            const int prow0 = (16 * wr + g) * PP;
            const int prow1 = (16 * wr + g + 8) * PP;
            const int dim0  = 16 * wc + g;

            #pragma unroll
            for (int kc = 0; kc < 4; ++kc) {
                const int kcol = 8 * kc + tg;
                unsigned a[4];
                a[0] = __float_as_uint(sP[prow0 + kcol]);
                a[1] = __float_as_uint(sP[prow1 + kcol]);
                a[2] = __float_as_uint(sP[prow0 + kcol + 4]);
                a[3] = __float_as_uint(sP[prow1 + kcol + 4]);

                const unsigned b00 = __float_as_uint(sV[kcol * VPF + dim0]);
                const unsigned b01 = __float_as_uint(sV[(kcol + 4) * VPF + dim0]);
                mma_tf32(acc0, a, b00, b01);

                const unsigned b10 = __float_as_uint(sV[kcol * VPF + dim0 + 8]);
                const unsigned b11 = __float_as_uint(sV[(kcol + 4) * VPF + dim0 + 8]);
                mma_tf32(acc1, a, b10, b11);
            }
        }
        __syncthreads();

        jcur = jnext;
        cur ^= 1;
    }

    // --- epilogue ---
    if (c == 0) sRow[r] = 1.f / l;
    __syncthreads();
    {
        const float invl0 = sRow[16 * wr + g];
        const float invl1 = sRow[16 * wr + g + 8];
        const int row0 = qi * BS + 16 * wr + g;
        const int d0   = 16 * wc + 2 * tg;
        float* o0 = out + head_off + (size_t)row0 * HDIM;
        float* o1 = o0 + 8 * HDIM;

        float2 t0, t1;
        t0.x = acc0[0] * invl0; t0.y = acc0[1] * invl0;
        t1.x = acc0[2] * invl1; t1.y = acc0[3] * invl1;
        *reinterpret_cast<float2*>(o0 + d0) = t0;
        *reinterpret_cast<float2*>(o1 + d0) = t1;
        t0.x = acc1[0] * invl0; t0.y = acc1[1] * invl0;
        t1.x = acc1[2] * invl1; t1.y = acc1[3] * invl1;
        *reinterpret_cast<float2*>(o0 + d0 + 8) = t0;
        *reinterpret_cast<float2*>(o1 + d0 + 8) = t1;
    }
}

// ---------------------------------------------------------------------------
extern "C" void kernel_launch(void* const* d_in, const int* in_sizes, int n_in,
                              void* d_out, int out_size) {
    (void)in_sizes; (void)n_in; (void)out_size;
    const float* q    = (const float*)d_in[0];
    const float* k    = (const float*)d_in[1];
    const float* v    = (const float*)d_in[2];
    const float* mask = (const float*)d_in[3];
    float* out        = (float*)d_out;

    const int smem_bytes = 2 * KTILE_B + 2 * VTILE_B + (BS * SP + BS * PP + BS) * 4;
    static bool attr_set = false;
    if (!attr_set) {
        cudaFuncSetAttribute(attn_kernel, cudaFuncAttributeMaxDynamicSharedMemorySize, smem_bytes);
        attr_set = true;
    }

    block_mask_kernel<<<HEADS, 1024>>>(mask);
    prep_kernel<<<dim3(NB, BATCH * HEADS), 256>>>(k);
    attn_kernel<<<dim3(NB, BATCH * HEADS), 256, smem_bytes>>>(q, v, out);
}

// round 9
// speedup vs baseline: 9.9639x; 1.0283x over previous
#include <cuda_runtime.h>
#include <math.h>
#include <stdint.h>

constexpr int BATCH = 8;
constexpr int HEADS = 16;
constexpr int SEQ   = 1024;
constexpr int HDIM  = 64;
constexpr int BS    = 32;
constexpr int NB    = SEQ / BS;

// Strides in the array's OWN element units; must be >= row data length (64).
constexpr int QP2 = 68;  // sQ2 row stride in float2 (hi,lo)
constexpr int KP2 = 68;  // K tile row stride in float2 (hi,lo)
constexpr int VPF = 72;  // V tile row stride in floats
constexpr int SP  = 40;  // score row stride (floats)
constexpr int PP  = 36;  // probs row stride (floats)

constexpr int QTILE_B = BS * QP2 * 8;  // 17408
constexpr int KTILE_B = BS * KP2 * 8;  // 17408
constexpr int VTILE_B = BS * VPF * 4;  // 9216

// dynamic smem layout (bytes)
constexpr int OFF_Q   = 0;
constexpr int OFF_K   = OFF_Q + QTILE_B;            // 17408
constexpr int OFF_V   = OFF_K + KTILE_B;            // 34816  (two buffers)
constexpr int OFF_S   = OFF_V + 2 * VTILE_B;        // 53248
constexpr int OFF_P   = OFF_S + BS * SP * 4;        // 58368
constexpr int OFF_ROW = OFF_P + BS * PP * 4;        // 62976
constexpr int SMEM_TOTAL = OFF_ROW + BS * 4;        // 63104

__device__ unsigned g_bm[HEADS * NB];
__device__ float2 g_Ksp[(size_t)BATCH * HEADS * NB * BS * KP2];  // pre-split K tiles

// ---------------------------------------------------------------------------
// Mask: reference mask is block-constant -> sample one element per block.
// ---------------------------------------------------------------------------
__global__ void block_mask_kernel(const float* __restrict__ mask) {
    const int h  = blockIdx.x;
    const int t  = threadIdx.x;      // 0..1023
    const int bi = t >> 5;
    const int bj = t & 31;
    const float val = mask[((size_t)h * SEQ + (size_t)bi * BS) * SEQ + (size_t)bj * BS];
    const unsigned bits = __ballot_sync(0xffffffffu, val != 0.f);
    if (bj == 0) g_bm[h * NB + bi] = bits | (1u << bi);
}

// ---------------------------------------------------------------------------
__device__ __forceinline__ float f2tf32f(float x) {
    unsigned r;
    asm("cvt.rna.tf32.f32 %0, %1;" : "=r"(r) : "f"(x));
    return __uint_as_float(r);
}
__device__ __forceinline__ void split_tf32(float x, unsigned& hi, unsigned& lo) {
    asm("cvt.rna.tf32.f32 %0, %1;" : "=r"(hi) : "f"(x));
    asm("cvt.rna.tf32.f32 %0, %1;" : "=r"(lo) : "f"(x - __uint_as_float(hi)));
}
__device__ __forceinline__ void mma_tf32(float* d, const unsigned* a, unsigned b0, unsigned b1) {
    asm volatile(
        "mma.sync.aligned.m16n8k8.row.col.f32.tf32.tf32.f32 "
        "{%0,%1,%2,%3},{%4,%5,%6,%7},{%8,%9},{%0,%1,%2,%3};"
        : "+f"(d[0]), "+f"(d[1]), "+f"(d[2]), "+f"(d[3])
        : "r"(a[0]), "r"(a[1]), "r"(a[2]), "r"(a[3]), "r"(b0), "r"(b1));
}
__device__ __forceinline__ void cp_async16(unsigned s, const void* g) {
    asm volatile("cp.async.cg.shared.global [%0], [%1], 16;" :: "r"(s), "l"(g));
}

// ---------------------------------------------------------------------------
// Preprocess: split K into (hi,lo) tf32 pairs in padded tile layout.
// ---------------------------------------------------------------------------
__global__ void prep_kernel(const float* __restrict__ k) {
    const int j  = blockIdx.x;
    const int bh = blockIdx.y;
    const int t  = threadIdx.x;

    const float* kg = k + ((size_t)bh * SEQ + (size_t)j * BS) * HDIM;
    float2* kd = g_Ksp + ((size_t)bh * NB + j) * BS * KP2;

    #pragma unroll
    for (int part = 0; part < 2; ++part) {
        const int idx = t + part * 256;
        const int row = idx >> 4;
        const int col = 4 * (idx & 15);
        float4 kv = *reinterpret_cast<const float4*>(kg + row * HDIM + col);
        unsigned h0, l0, h1, l1, h2, l2, h3, l3;
        split_tf32(kv.x, h0, l0); split_tf32(kv.y, h1, l1);
        split_tf32(kv.z, h2, l2); split_tf32(kv.w, h3, l3);
        float4* dst = reinterpret_cast<float4*>(&kd[row * KP2 + col]);
        dst[0] = make_float4(__uint_as_float(h0), __uint_as_float(l0),
                             __uint_as_float(h1), __uint_as_float(l1));
        dst[1] = make_float4(__uint_as_float(h2), __uint_as_float(l2),
                             __uint_as_float(h3), __uint_as_float(l3));
    }
}

// ---------------------------------------------------------------------------
// Block-sparse causal flash attention. Q in smem (pre-split once/CTA),
// single-buffer K, double-buffer V, 3 barriers/iter, 3 CTAs/SM.
// ---------------------------------------------------------------------------
__global__ __launch_bounds__(256, 3)
void attn_kernel(const float* __restrict__ q,
                 const float* __restrict__ v,
                 float* __restrict__ out) {
    const int qi = blockIdx.x;
    const int bh = blockIdx.y;
    const int h  = bh & (HEADS - 1);
    const int t  = threadIdx.x;
    const int w    = t >> 5;
    const int lane = t & 31;
    const int g  = lane >> 2;
    const int tg = lane & 3;
    const int wr = w >> 2;
    const int wc = w & 3;
    const int r  = t >> 3;
    const int c  = t & 7;

    extern __shared__ char smem[];
    float2* sQ2 = reinterpret_cast<float2*>(smem + OFF_Q);
    float2* sK2 = reinterpret_cast<float2*>(smem + OFF_K);
    float*  sVb = reinterpret_cast<float*>(smem + OFF_V);
    float*  sS  = reinterpret_cast<float*>(smem + OFF_S);
    float*  sP  = reinterpret_cast<float*>(smem + OFF_P);
    float*  sRow= reinterpret_cast<float*>(smem + OFF_ROW);

    const size_t head_off = (size_t)bh * SEQ * HDIM;

    // --- Stage Q tile, split to (hi,lo), into smem once ---
    {
        const float* qg = q + head_off + (size_t)qi * BS * HDIM;
        #pragma unroll
        for (int part = 0; part < 2; ++part) {
            const int idx = t + part * 256;
            const int row = idx >> 4;
            const int col = 4 * (idx & 15);
            float4 qv = *reinterpret_cast<const float4*>(qg + row * HDIM + col);
            unsigned h0, l0, h1, l1, h2, l2, h3, l3;
            split_tf32(qv.x, h0, l0); split_tf32(qv.y, h1, l1);
            split_tf32(qv.z, h2, l2); split_tf32(qv.w, h3, l3);
            float4* dst = reinterpret_cast<float4*>(&sQ2[row * QP2 + col]);
            dst[0] = make_float4(__uint_as_float(h0), __uint_as_float(l0),
                                 __uint_as_float(h1), __uint_as_float(l1));
            dst[1] = make_float4(__uint_as_float(h2), __uint_as_float(l2),
                                 __uint_as_float(h3), __uint_as_float(l3));
        }
    }

    float m = -INFINITY, l = 0.f;
    float acc0[4] = {0.f, 0.f, 0.f, 0.f};
    float acc1[4] = {0.f, 0.f, 0.f, 0.f};

    unsigned rem = g_bm[h * NB + qi] & (unsigned)((2ull << qi) - 1ull);

    const char* ktiles = reinterpret_cast<const char*>(g_Ksp + (size_t)bh * NB * BS * KP2);
    const char* vsrc   = reinterpret_cast<const char*>(v + head_off);
    const unsigned smem_u = (unsigned)__cvta_generic_to_shared(smem);

    auto stage = [&](int vbuf, int j) {
        const char* gk = ktiles + (size_t)j * KTILE_B;
        #pragma unroll
        for (int ofs = 0; ofs < KTILE_B; ofs += 4096) {
            const int o = ofs + t * 16;
            if (o < KTILE_B) cp_async16(smem_u + OFF_K + o, gk + o);
        }
        const char* gv = vsrc + (size_t)j * BS * HDIM * 4;
        const unsigned sv = smem_u + OFF_V + vbuf * VTILE_B;
        #pragma unroll
        for (int part = 0; part < 2; ++part) {
            const int idx = t + part * 256;
            const int row = idx >> 4;
            const int col = idx & 15;
            cp_async16(sv + row * (VPF * 4) + col * 16, gv + row * 256 + col * 16);
        }
        asm volatile("cp.async.commit_group;");
    };

    int jcur = __ffs(rem) - 1;
    rem &= rem - 1;
    stage(0, jcur);
    int cur = 0;

    const int qrow0 = (16 * wr + g) * QP2;
    const int qrow1 = (16 * wr + g + 8) * QP2;

    while (jcur >= 0) {
        asm volatile("cp.async.wait_group 0;");
        __syncthreads();   // A: K(jcur) + V(buf cur) visible; Q visible (1st iter)

        const float* sV = sVb + cur * BS * VPF;

        // --- scores: 3-pass tf32, Q frags from smem, 3 indep mma chains ---
        {
            float sa[4] = {0.f, 0.f, 0.f, 0.f};
            float sb[4] = {0.f, 0.f, 0.f, 0.f};
            float sc[4] = {0.f, 0.f, 0.f, 0.f};
            const int krow = 8 * wc + g;
            const float2* kb = &sK2[krow * KP2];
            #pragma unroll
            for (int kc = 0; kc < 8; ++kc) {
                const int c0 = 8 * kc + tg;
                const float2 q00 = sQ2[qrow0 + c0];
                const float2 q10 = sQ2[qrow1 + c0];
                const float2 q01 = sQ2[qrow0 + c0 + 4];
                const float2 q11 = sQ2[qrow1 + c0 + 4];
                unsigned ah[4], al[4];
                ah[0] = __float_as_uint(q00.x); al[0] = __float_as_uint(q00.y);
                ah[1] = __float_as_uint(q10.x); al[1] = __float_as_uint(q10.y);
                ah[2] = __float_as_uint(q01.x); al[2] = __float_as_uint(q01.y);
                ah[3] = __float_as_uint(q11.x); al[3] = __float_as_uint(q11.y);

                const float2 e0 = kb[c0];
                const float2 e1 = kb[c0 + 4];
                const unsigned bh0 = __float_as_uint(e0.x), bl0 = __float_as_uint(e0.y);
                const unsigned bh1 = __float_as_uint(e1.x), bl1 = __float_as_uint(e1.y);
                mma_tf32(sa, ah, bh0, bh1);
                mma_tf32(sb, ah, bl0, bl1);
                mma_tf32(sc, al, bh0, bh1);
            }
            const int row0 = 16 * wr + g;
            const int col0 = 8 * wc + 2 * tg;
            sS[row0 * SP + col0]           = sa[0] + (sb[0] + sc[0]);
            sS[row0 * SP + col0 + 1]       = sa[1] + (sb[1] + sc[1]);
            sS[(row0 + 8) * SP + col0]     = sa[2] + (sb[2] + sc[2]);
            sS[(row0 + 8) * SP + col0 + 1] = sa[3] + (sb[3] + sc[3]);
        }
        __syncthreads();   // B: all K/sS accesses ordered; safe to restage K

        int jnext = -1;
        if (rem) { jnext = __ffs(rem) - 1; rem &= rem - 1; }
        if (jnext >= 0) stage(cur ^ 1, jnext);   // overlaps softmax + PV

        // --- softmax (exact fp32) ---
        {
            float s0 = sS[r * SP + c];
            float s1 = sS[r * SP + c + 8];
            float s2 = sS[r * SP + c + 16];
            float s3 = sS[r * SP + c + 24];
            if (jcur == qi) {
                if (c      > r) s0 = -INFINITY;
                if (c +  8 > r) s1 = -INFINITY;
                if (c + 16 > r) s2 = -INFINITY;
                if (c + 24 > r) s3 = -INFINITY;
            }
            float ms = fmaxf(fmaxf(s0, s1), fmaxf(s2, s3));
            #pragma unroll
            for (int off = 4; off; off >>= 1)
                ms = fmaxf(ms, __shfl_xor_sync(0xffffffffu, ms, off, 8));

            const float mn    = fmaxf(m, ms);
            const float scale = __expf(m - mn);
            const float p0 = __expf(s0 - mn);
            const float p1 = __expf(s1 - mn);
            const float p2 = __expf(s2 - mn);
            const float p3 = __expf(s3 - mn);

            float lb = p0 + p1 + p2 + p3;
            #pragma unroll
            for (int off = 4; off; off >>= 1)
                lb += __shfl_xor_sync(0xffffffffu, lb, off, 8);

            l = l * scale + lb;
            m = mn;

            sP[r * PP + c]      = f2tf32f(p0);
            sP[r * PP + c + 8]  = f2tf32f(p1);
            sP[r * PP + c + 16] = f2tf32f(p2);
            sP[r * PP + c + 24] = f2tf32f(p3);
            if (c == 0) sRow[r] = scale;
        }
        __syncthreads();   // C: sP/sRow visible

        // --- PV: single-pass tf32 ---
        {
            const float scale0 = sRow[16 * wr + g];
            const float scale1 = sRow[16 * wr + g + 8];
            acc0[0] *= scale0; acc0[1] *= scale0; acc0[2] *= scale1; acc0[3] *= scale1;
            acc1[0] *= scale0; acc1[1] *= scale0; acc1[2] *= scale1; acc1[3] *= scale1;

            const int prow0 = (16 * wr + g) * PP;
            const int prow1 = (16 * wr + g + 8) * PP;
            const int dim0  = 16 * wc + g;

            #pragma unroll
            for (int kc = 0; kc < 4; ++kc) {
                const int kcol = 8 * kc + tg;
                unsigned a[4];
                a[0] = __float_as_uint(sP[prow0 + kcol]);
                a[1] = __float_as_uint(sP[prow1 + kcol]);
                a[2] = __float_as_uint(sP[prow0 + kcol + 4]);
                a[3] = __float_as_uint(sP[prow1 + kcol + 4]);

                const unsigned b00 = __float_as_uint(sV[kcol * VPF + dim0]);
                const unsigned b01 = __float_as_uint(sV[(kcol + 4) * VPF + dim0]);
                mma_tf32(acc0, a, b00, b01);

                const unsigned b10 = __float_as_uint(sV[kcol * VPF + dim0 + 8]);
                const unsigned b11 = __float_as_uint(sV[(kcol + 4) * VPF + dim0 + 8]);
                mma_tf32(acc1, a, b10, b11);
            }
        }
        // no barrier: next iter's wait_group + barrier A orders everything.

        jcur = jnext;
        cur ^= 1;
    }

    __syncthreads();   // all PV reads of sRow done before overwrite
    if (c == 0) sRow[r] = 1.f / l;
    __syncthreads();
    {
        const float invl0 = sRow[16 * wr + g];
        const float invl1 = sRow[16 * wr + g + 8];
        const int row0 = qi * BS + 16 * wr + g;
        const int d0   = 16 * wc + 2 * tg;
        float* o0 = out + head_off + (size_t)row0 * HDIM;
        float* o1 = o0 + 8 * HDIM;

        float2 t0, t1;
        t0.x = acc0[0] * invl0; t0.y = acc0[1] * invl0;
        t1.x = acc0[2] * invl1; t1.y = acc0[3] * invl1;
        *reinterpret_cast<float2*>(o0 + d0) = t0;
        *reinterpret_cast<float2*>(o1 + d0) = t1;
        t0.x = acc1[0] * invl0; t0.y = acc1[1] * invl0;
        t1.x = acc1[2] * invl1; t1.y = acc1[3] * invl1;
        *reinterpret_cast<float2*>(o0 + d0 + 8) = t0;
        *reinterpret_cast<float2*>(o1 + d0 + 8) = t1;
    }
}

// ---------------------------------------------------------------------------
extern "C" void kernel_launch(void* const* d_in, const int* in_sizes, int n_in,
                              void* d_out, int out_size) {
    (void)in_sizes; (void)n_in; (void)out_size;
    const float* q    = (const float*)d_in[0];
    const float* k    = (const float*)d_in[1];
    const float* v    = (const float*)d_in[2];
    const float* mask = (const float*)d_in[3];
    float* out        = (float*)d_out;

    static bool attr_set = false;
    if (!attr_set) {
        cudaFuncSetAttribute(attn_kernel, cudaFuncAttributeMaxDynamicSharedMemorySize, SMEM_TOTAL);
        attr_set = true;
    }

    block_mask_kernel<<<HEADS, 1024>>>(mask);
    prep_kernel<<<dim3(NB, BATCH * HEADS), 256>>>(k);
    attn_kernel<<<dim3(NB, BATCH * HEADS), 256, SMEM_TOTAL>>>(q, v, out);
}